// round 4
// baseline (speedup 1.0000x reference)
#include <cuda_runtime.h>

// LocalAttention: B=8,H=8,T=8192,E=64, 128 buckets of 64, window = prev+cur bucket (128),
// causal within window, bucket 0's backward half is padding. No 1/sqrt(E) scaling.

#define T_SEQ   8192
#define E_DIM   64
#define NBUCK   128
#define BSIZE   64      // bucket size (q rows per tile)
#define WIN     128     // k/v window rows per tile
#define BH      64

#define KT_STRIDE 129                       // padded stride for transposed K
#define OFF_KT  0                           // Kt: 64 x 129 floats   (33,024 B)
#define OFF_Q   (64 * KT_STRIDE)            // Q : 64 x 64  floats   (16,384 B)
#define OFF_V   (OFF_Q + 64 * 64)           // V : 128 x 64 floats   (32,768 B)
#define OFF_P   0                           // P : 64 x 128 floats, overlays Kt after sync
#define SMEM_FLOATS (OFF_V + 128 * 64)      // 20544 floats = 82,176 B

typedef unsigned long long ull;

__device__ __forceinline__ ull pk2(float x, float y) {
    ull r; asm("mov.b64 %0, {%1,%2};" : "=l"(r) : "f"(x), "f"(y)); return r;
}
__device__ __forceinline__ void upk2(ull v, float& x, float& y) {
    asm("mov.b64 {%0,%1}, %2;" : "=f"(x), "=f"(y) : "l"(v));
}
// packed dual-FMA: d.lo += a.lo*b.lo ; d.hi += a.hi*b.hi   (Blackwell f32x2 pipe)
__device__ __forceinline__ void fma2(ull& d, ull a, ull b) {
    asm("fma.rn.f32x2 %0, %1, %2, %0;" : "+l"(d) : "l"(a), "l"(b));
}

extern __shared__ float sm[];

__global__ __launch_bounds__(128, 2)
void local_attn_kernel(const float* __restrict__ q,
                       const float* __restrict__ k,
                       const float* __restrict__ v,
                       float* __restrict__ out)
{
    const int w   = blockIdx.x;      // bucket
    const int bh  = blockIdx.y;      // batch*head
    const int tid = threadIdx.x;
    const int tx  = tid & 15;        // 16 column groups
    const int ty  = tid >> 4;        // 8 row groups

    const size_t base = (size_t)bh * (T_SEQ * E_DIM);
    const float* gq = q + base + (size_t)w * BSIZE * E_DIM;
    const float* gk = k + base;
    const float* gv = v + base;

    // ---------------- Load Q (row-major, direct float4 copy) ----------------
    #pragma unroll
    for (int it = 0; it < 8; ++it) {
        int idx = tid + it * 128;          // 1024 float4s
        int i   = idx >> 4;
        int c4  = idx & 15;
        float4 val = *(const float4*)(gq + i * E_DIM + c4 * 4);
        *(float4*)(sm + OFF_Q + i * E_DIM + c4 * 4) = val;
    }

    // ------- Load K (transposed, stride 129) and V (row-major), zero-pad ----
    const int row0 = (w - 1) * BSIZE;      // global seq row of window col 0
    #pragma unroll
    for (int it = 0; it < 16; ++it) {
        int idx = tid + it * 128;          // 2048 float4s
        int t   = idx >> 4;                // window row 0..127
        int c4  = idx & 15;
        int gr  = row0 + t;
        float4 kv4 = make_float4(0.f, 0.f, 0.f, 0.f);
        float4 vv4 = make_float4(0.f, 0.f, 0.f, 0.f);
        if (gr >= 0) {
            kv4 = *(const float4*)(gk + (size_t)gr * E_DIM + c4 * 4);
            vv4 = *(const float4*)(gv + (size_t)gr * E_DIM + c4 * 4);
        }
        int kk = c4 * 4;
        sm[OFF_KT + (kk + 0) * KT_STRIDE + t] = kv4.x;
        sm[OFF_KT + (kk + 1) * KT_STRIDE + t] = kv4.y;
        sm[OFF_KT + (kk + 2) * KT_STRIDE + t] = kv4.z;
        sm[OFF_KT + (kk + 3) * KT_STRIDE + t] = kv4.w;
        *(float4*)(sm + OFF_V + t * E_DIM + c4 * 4) = vv4;
    }
    __syncthreads();

    // ---------------- QK^T: 8x8 register tile per thread ----------------
    // rows i = 8*ty + r ; cols j = tx + 16*m (strided -> conflict-free P stores)
    ull acc[8][4];
    #pragma unroll
    for (int r = 0; r < 8; ++r)
        #pragma unroll
        for (int h = 0; h < 4; ++h) acc[r][h] = 0ull;

    const float* qrow = sm + OFF_Q + (ty * 8) * E_DIM;
    const float* kt   = sm + OFF_KT + tx;

    #pragma unroll 4
    for (int kk = 0; kk < E_DIM; ++kk) {
        float kv[8];
        #pragma unroll
        for (int m = 0; m < 8; ++m) kv[m] = kt[kk * KT_STRIDE + 16 * m];
        ull b[4];
        #pragma unroll
        for (int h = 0; h < 4; ++h) b[h] = pk2(kv[2 * h], kv[2 * h + 1]);
        #pragma unroll
        for (int r = 0; r < 8; ++r) {
            float qv = qrow[r * E_DIM + kk];
            ull a = pk2(qv, qv);
            fma2(acc[r][0], a, b[0]);
            fma2(acc[r][1], a, b[1]);
            fma2(acc[r][2], a, b[2]);
            fma2(acc[r][3], a, b[3]);
        }
    }

    // ---------------- Softmax (masks + row reductions in registers) ----------------
    // acc[r][h] = (col tx+32h , col tx+32h+16)  -> logical m = 2h, 2h+1 (j = tx+16m)
    const bool w0ok = (w > 0);   // bucket 0: cols j<64 are padding -> masked
    float p[8][8];
    float inv[8];
    #pragma unroll
    for (int r = 0; r < 8; ++r) {
        const int i = ty * 8 + r;
        #pragma unroll
        for (int h = 0; h < 4; ++h) upk2(acc[r][h], p[r][2 * h], p[r][2 * h + 1]);

        float mx = -1e30f;
        #pragma unroll
        for (int m = 0; m < 8; ++m) {
            int j = tx + 16 * m;
            bool ok = (j <= i + 64) && (w0ok || j >= 64);   // causal + pad
            p[r][m] = ok ? p[r][m] : -1e30f;
            mx = fmaxf(mx, p[r][m]);
        }
        // reduce over the 16 col-lanes (xor 1,2,4,8 stays inside each 16-lane group)
        mx = fmaxf(mx, __shfl_xor_sync(0xffffffffu, mx, 1));
        mx = fmaxf(mx, __shfl_xor_sync(0xffffffffu, mx, 2));
        mx = fmaxf(mx, __shfl_xor_sync(0xffffffffu, mx, 4));
        mx = fmaxf(mx, __shfl_xor_sync(0xffffffffu, mx, 8));

        float s = 0.f;
        #pragma unroll
        for (int m = 0; m < 8; ++m) {
            float e = __expf(p[r][m] - mx);   // masked entries -> exp(-1e30) == 0
            p[r][m] = e;
            s += e;
        }
        s += __shfl_xor_sync(0xffffffffu, s, 1);
        s += __shfl_xor_sync(0xffffffffu, s, 2);
        s += __shfl_xor_sync(0xffffffffu, s, 4);
        s += __shfl_xor_sync(0xffffffffu, s, 8);
        inv[r] = __fdividef(1.0f, s);
    }

    __syncthreads();   // all Kt/Q reads done -> safe to overlay P on Kt region

    // ---------------- Store normalized P (row-major; lanes vary tx -> conflict-free)
    #pragma unroll
    for (int r = 0; r < 8; ++r) {
        const int i = ty * 8 + r;
        const float sc = inv[r];
        #pragma unroll
        for (int m = 0; m < 8; ++m)
            sm[OFF_P + i * WIN + tx + 16 * m] = p[r][m] * sc;
    }
    __syncthreads();

    // ---------------- P @ V : 8 rows x 4 cols per thread ----------------
    // P reads broadcast over tx; V reads one 16B vector per lane (conflict-free)
    ull ao[8][2];
    #pragma unroll
    for (int r = 0; r < 8; ++r) { ao[r][0] = 0ull; ao[r][1] = 0ull; }

    const float* pr = sm + OFF_P + (ty * 8) * WIN;
    const float* vc = sm + OFF_V + tx * 4;

    #pragma unroll 4
    for (int j = 0; j < WIN; ++j) {
        ulonglong2 bv = *(const ulonglong2*)(vc + j * E_DIM);  // (v0,v1),(v2,v3)
        #pragma unroll
        for (int r = 0; r < 8; ++r) {
            float pv = pr[r * WIN + j];
            ull a = pk2(pv, pv);
            fma2(ao[r][0], a, bv.x);
            fma2(ao[r][1], a, bv.y);
        }
    }

    // ---------------- Write output ----------------
    float* go = out + base + (size_t)w * BSIZE * E_DIM;
    #pragma unroll
    for (int r = 0; r < 8; ++r) {
        float4 o;
        upk2(ao[r][0], o.x, o.y);
        upk2(ao[r][1], o.z, o.w);
        *(float4*)(go + (ty * 8 + r) * E_DIM + tx * 4) = o;
    }
}

extern "C" void kernel_launch(void* const* d_in, const int* in_sizes, int n_in,
                              void* d_out, int out_size)
{
    const float* q = (const float*)d_in[0];
    const float* k = (const float*)d_in[1];
    const float* v = (const float*)d_in[2];
    float* o = (float*)d_out;

    const size_t smem_bytes = SMEM_FLOATS * sizeof(float);   // 82,176 B
    cudaFuncSetAttribute(local_attn_kernel,
                         cudaFuncAttributeMaxDynamicSharedMemorySize,
                         (int)smem_bytes);

    dim3 grid(NBUCK, BH);       // 128 buckets x 64 (batch*head) = 8192 tiles
    local_attn_kernel<<<grid, 128, smem_bytes>>>(q, k, v, o);
}